// round 17
// baseline (speedup 1.0000x reference)
#include <cuda_runtime.h>
#include <cuda_bf16.h>
#include <cstdint>

typedef __nv_bfloat16 bf16;

#define BATCH 2
#define SEQ 2048
#define DMODEL 768
#define NH 12
#define DKH 64
#define MROWS (BATCH*SEQ)

// ---------------- scratch (no allocs allowed) ----------------
__device__ __align__(16) bf16 g_xhi[3u*MROWS*DMODEL];
__device__ __align__(16) bf16 g_xlo[3u*MROWS*DMODEL];
__device__ __align__(16) bf16 g_whi[4u*DMODEL*DMODEL];
__device__ __align__(16) bf16 g_wlo[4u*DMODEL*DMODEL];
__device__ __align__(16) float g_qp[(size_t)MROWS*DMODEL];   // [B,H,S,D] tf32-rounded
__device__ __align__(16) float g_kp[(size_t)MROWS*DMODEL];   // [B,H,S,D]
__device__ __align__(16) float g_vpt[(size_t)MROWS*DMODEL];  // [B,H,D,S] transposed
__device__ __align__(16) bf16 g_chi[MROWS*DMODEL];
__device__ __align__(16) bf16 g_clo[MROWS*DMODEL];
__device__ __align__(16) bf16 g_mbias[(size_t)SEQ*SEQ];

// exp(x*0.125 + b) = exp2(x*C + b*LOG2E)
#define SCALE_LOG2E 0.18033688011112042f
#define NEG_BIAS   (-1.4426950408889634e9f)

// ---------------- helpers ----------------
__device__ __forceinline__ uint32_t smem_u32(const void* p) {
    uint32_t a;
    asm("{ .reg .u64 t; cvta.to.shared.u64 t, %1; cvt.u32.u64 %0, t; }" : "=r"(a) : "l"(p));
    return a;
}
__device__ __forceinline__ void ldsm4(uint32_t r[4], uint32_t a) {
    asm volatile("ldmatrix.sync.aligned.m8n8.x4.shared.b16 {%0,%1,%2,%3}, [%4];"
        : "=r"(r[0]), "=r"(r[1]), "=r"(r[2]), "=r"(r[3]) : "r"(a));
}
__device__ __forceinline__ void mma16816(float c[4], uint32_t a0, uint32_t a1, uint32_t a2, uint32_t a3,
                                         uint32_t b0, uint32_t b1) {
    asm volatile("mma.sync.aligned.m16n8k16.row.col.f32.bf16.bf16.f32 "
        "{%0,%1,%2,%3}, {%4,%5,%6,%7}, {%8,%9}, {%0,%1,%2,%3};"
        : "+f"(c[0]), "+f"(c[1]), "+f"(c[2]), "+f"(c[3])
        : "r"(a0), "r"(a1), "r"(a2), "r"(a3), "r"(b0), "r"(b1));
}
__device__ __forceinline__ void mma_tf32(float c[4], const uint32_t a[4], uint32_t b0, uint32_t b1) {
    asm volatile("mma.sync.aligned.m16n8k8.row.col.f32.tf32.tf32.f32 "
        "{%0,%1,%2,%3}, {%4,%5,%6,%7}, {%8,%9}, {%0,%1,%2,%3};"
        : "+f"(c[0]), "+f"(c[1]), "+f"(c[2]), "+f"(c[3])
        : "r"(a[0]), "r"(a[1]), "r"(a[2]), "r"(a[3]), "r"(b0), "r"(b1));
}
__device__ __forceinline__ uint32_t packbf(float x0, float x1) {
    uint32_t r;
    asm("cvt.rn.bf16x2.f32 %0, %1, %2;" : "=r"(r) : "f"(x1), "f"(x0));
    return r;
}
__device__ __forceinline__ void hilo(float v, float& h, float& l) {
    h = __bfloat162float(__float2bfloat16_rn(v));
    l = v - h;
}
__device__ __forceinline__ float tf32r(float v) {
    uint32_t r;
    asm("cvt.rna.tf32.f32 %0, %1;" : "=r"(r) : "f"(v));
    return __uint_as_float(r);
}
__device__ __forceinline__ uint32_t tf32u(float v) {
    uint32_t r;
    asm("cvt.rna.tf32.f32 %0, %1;" : "=r"(r) : "f"(v));
    return r;
}
__device__ __forceinline__ uint32_t lds32(uint32_t a) {
    uint32_t v;
    asm volatile("ld.shared.b32 %0, [%1];" : "=r"(v) : "r"(a));
    return v;
}
__device__ __forceinline__ void sts64(uint32_t a, uint32_t v0, uint32_t v1) {
    asm volatile("st.shared.v2.b32 [%0], {%1, %2};" :: "r"(a), "r"(v0), "r"(v1) : "memory");
}
__device__ __forceinline__ void cpa16(uint32_t s, const void* g) {
    asm volatile("cp.async.cg.shared.global [%0], [%1], 16;" :: "r"(s), "l"(g) : "memory");
}
#define CP_COMMIT() asm volatile("cp.async.commit_group;" ::: "memory")
#define CP_WAIT0()  asm volatile("cp.async.wait_group 0;" ::: "memory")

// ---------------- conversion kernels ----------------
__global__ __launch_bounds__(256) void cvt_in_kernel(
    const float* __restrict__ q, const float* __restrict__ k, const float* __restrict__ v)
{
    const float* src = blockIdx.z == 0 ? q : blockIdx.z == 1 ? k : v;
    bf16* hi = g_xhi + (size_t)blockIdx.z * MROWS * DMODEL;
    bf16* lo = g_xlo + (size_t)blockIdx.z * MROWS * DMODEL;
    size_t i = ((size_t)blockIdx.x * 256 + threadIdx.x) * 4;
    float4 f = *(const float4*)(src + i);
    float h0,l0,h1,l1,h2,l2,h3,l3;
    hilo(f.x,h0,l0); hilo(f.y,h1,l1); hilo(f.z,h2,l2); hilo(f.w,h3,l3);
    *(uint2*)(hi + i) = make_uint2(packbf(f.x, f.y), packbf(f.z, f.w));
    *(uint2*)(lo + i) = make_uint2(packbf(l0, l1), packbf(l2, l3));
}

__global__ __launch_bounds__(256) void cvt_w_kernel(
    const float* __restrict__ wq, const float* __restrict__ wk,
    const float* __restrict__ wv, const float* __restrict__ wo)
{
    const float* src = blockIdx.z == 0 ? wq : blockIdx.z == 1 ? wk : blockIdx.z == 2 ? wv : wo;
    bf16* hi = g_whi + (size_t)blockIdx.z * DMODEL * DMODEL;
    bf16* lo = g_wlo + (size_t)blockIdx.z * DMODEL * DMODEL;
    size_t i = ((size_t)blockIdx.x * 256 + threadIdx.x) * 4;
    float4 f = *(const float4*)(src + i);
    float h0,l0,h1,l1,h2,l2,h3,l3;
    hilo(f.x,h0,l0); hilo(f.y,h1,l1); hilo(f.z,h2,l2); hilo(f.w,h3,l3);
    *(uint2*)(hi + i) = make_uint2(packbf(f.x, f.y), packbf(f.z, f.w));
    *(uint2*)(lo + i) = make_uint2(packbf(l0, l1), packbf(l2, l3));
}

__global__ __launch_bounds__(256) void cvt_mask_kernel(const int* __restrict__ mask)
{
    size_t i = ((size_t)blockIdx.x * 256 + threadIdx.x) * 4;
    int4 m = *(const int4*)(mask + i);
    float v0 = m.x ? 0.0f : NEG_BIAS;
    float v1 = m.y ? 0.0f : NEG_BIAS;
    float v2 = m.z ? 0.0f : NEG_BIAS;
    float v3 = m.w ? 0.0f : NEG_BIAS;
    *(uint2*)(g_mbias + i) = make_uint2(packbf(v0, v1), packbf(v2, v3));
}

// ---------------- GEMM: 256x128 CTA, 8 warps, 64x64 warp tiles (r12/r16 proven) ----------------
#define HS 40
#define ATB_G (256*HS*2)
#define BTB_G (128*HS*2)
#define GEMM_SMEM (2*ATB_G + 2*BTB_G)

template<bool OUT>
__global__ __launch_bounds__(256, 1) void gemm_mma_kernel(
    const float* __restrict__ bq, const float* __restrict__ bk,
    const float* __restrict__ bv, const float* __restrict__ bo,
    float* __restrict__ outp)
{
    extern __shared__ char smc[];
    const uint32_t sb = smem_u32(smc);
    const int t = threadIdx.x, lane = t & 31, wid = t >> 5;
    const int wm = wid >> 1, wn = wid & 1;
    const int z = OUT ? 3 : blockIdx.z;

    const bf16 *Ahi, *Alo;
    if (OUT) { Ahi = g_chi; Alo = g_clo; }
    else { Ahi = g_xhi + (size_t)z*MROWS*DMODEL; Alo = g_xlo + (size_t)z*MROWS*DMODEL; }
    const bf16* Bhi = g_whi + (size_t)z*DMODEL*DMODEL;
    const bf16* Blo = g_wlo + (size_t)z*DMODEL*DMODEL;
    const float* bias = OUT ? bo : (z == 0 ? bq : z == 1 ? bk : bv);

    const int bm = blockIdx.y * 256;
    const int bn = blockIdx.x * 128;

    float acc[4][8][4] = {};

    const int arow = t >> 2, ac8 = (t & 3) * 8;
    uint4 bufAh[4], bufAl[4], bufBh[2], bufBl[2];

    auto ldg_chunk = [&](int k0) {
        #pragma unroll
        for (int u = 0; u < 4; u++) {
            size_t off = (size_t)(bm + arow + 64*u)*DMODEL + k0 + ac8;
            bufAh[u] = *(const uint4*)(Ahi + off);
            bufAl[u] = *(const uint4*)(Alo + off);
        }
        #pragma unroll
        for (int u = 0; u < 2; u++) {
            size_t off = (size_t)(bn + arow + 64*u)*DMODEL + k0 + ac8;
            bufBh[u] = *(const uint4*)(Bhi + off);
            bufBl[u] = *(const uint4*)(Blo + off);
        }
    };
    auto sts_chunk = [&]() {
        #pragma unroll
        for (int u = 0; u < 4; u++) {
            uint32_t so = ((arow + 64*u)*HS + ac8)*2;
            *(uint4*)(smc + so) = bufAh[u];
            *(uint4*)(smc + ATB_G + so) = bufAl[u];
        }
        #pragma unroll
        for (int u = 0; u < 2; u++) {
            uint32_t so = ((arow + 64*u)*HS + ac8)*2;
            *(uint4*)(smc + 2*ATB_G + so) = bufBh[u];
            *(uint4*)(smc + 2*ATB_G + BTB_G + so) = bufBl[u];
        }
    };

    ldg_chunk(0);

    for (int c = 0; c < 24; c++) {
        __syncthreads();
        sts_chunk();
        __syncthreads();
        if (c < 23) ldg_chunk((c + 1) * 32);

        #pragma unroll
        for (int ks = 0; ks < 2; ks++) {
            uint32_t ah[4][4], al[4][4];
            #pragma unroll
            for (int am = 0; am < 4; am++) {
                uint32_t ad = sb + ((64*wm + 16*am + (lane & 15))*HS + 16*ks + (lane >> 4)*8)*2;
                ldsm4(ah[am], ad);
                ldsm4(al[am], ad + ATB_G);
            }
            #pragma unroll
            for (int bp = 0; bp < 4; bp++) {
                uint32_t bd = sb + 2*ATB_G +
                    ((64*wn + 16*bp + (lane & 7) + ((lane >> 4) & 1)*8)*HS + 16*ks + ((lane >> 3) & 1)*8)*2;
                uint32_t bh[4], bl[4];
                ldsm4(bh, bd);
                ldsm4(bl, bd + BTB_G);
                #pragma unroll
                for (int fi = 0; fi < 2; fi++)
                    #pragma unroll
                    for (int am = 0; am < 4; am++)
                        mma16816(acc[am][2*bp+fi], ah[am][0], ah[am][1], ah[am][2], ah[am][3], bh[2*fi], bh[2*fi+1]);
                #pragma unroll
                for (int fi = 0; fi < 2; fi++)
                    #pragma unroll
                    for (int am = 0; am < 4; am++)
                        mma16816(acc[am][2*bp+fi], ah[am][0], ah[am][1], ah[am][2], ah[am][3], bl[2*fi], bl[2*fi+1]);
                #pragma unroll
                for (int fi = 0; fi < 2; fi++)
                    #pragma unroll
                    for (int am = 0; am < 4; am++)
                        mma16816(acc[am][2*bp+fi], al[am][0], al[am][1], al[am][2], al[am][3], bh[2*fi], bh[2*fi+1]);
            }
        }
    }

    // epilogue: QKV -> tf32-rounded fp32 (V transposed); OUT -> final fp32
    const int rg = lane >> 2, cq = lane & 3;
    #pragma unroll
    for (int am = 0; am < 4; am++) {
        const int m1 = bm + 64*wm + 16*am + rg;
        const int m2 = m1 + 8;
        #pragma unroll
        for (int nf = 0; nf < 8; nf++) {
            const int n = bn + 64*wn + 8*nf + 2*cq;
            const float bb0 = bias[n], bb1 = bias[n+1];
            float v00 = acc[am][nf][0] + bb0, v01 = acc[am][nf][1] + bb1;
            float v10 = acc[am][nf][2] + bb0, v11 = acc[am][nf][3] + bb1;
            if (OUT) {
                *(float2*)(outp + (size_t)m1*DMODEL + n) = make_float2(v00, v01);
                *(float2*)(outp + (size_t)m2*DMODEL + n) = make_float2(v10, v11);
            } else {
                const int hh = n >> 6, d = n & 63;
                const int b1_ = m1 >> 11, s1_ = m1 & (SEQ-1);
                const int b2_ = m2 >> 11, s2_ = m2 & (SEQ-1);
                if (z < 2) {
                    float* D = (z == 0) ? g_qp : g_kp;
                    size_t i1 = ((size_t)(b1_*NH + hh)*SEQ + s1_)*DKH + d;
                    size_t i2 = ((size_t)(b2_*NH + hh)*SEQ + s2_)*DKH + d;
                    *(float2*)(D + i1) = make_float2(tf32r(v00), tf32r(v01));
                    *(float2*)(D + i2) = make_float2(tf32r(v10), tf32r(v11));
                } else {
                    size_t j1 = ((size_t)(b1_*NH + hh)*DKH + d)*SEQ + s1_;
                    size_t j2 = ((size_t)(b2_*NH + hh)*DKH + d)*SEQ + s2_;
                    g_vpt[j1]       = tf32r(v00);
                    g_vpt[j1 + SEQ] = tf32r(v01);
                    g_vpt[j2]       = tf32r(v10);
                    g_vpt[j2 + SEQ] = tf32r(v11);
                }
            }
        }
    }
}

// ---------------- flash attention: tf32 single-MMA, 64 q-rows, 4 warps, k-tile 32 ----------------
#define KST 68                         // Q/K row stride (floats)
#define VST 36                         // V^T row stride (floats)
#define PST 36                         // P row stride (floats)
#define AQ_B (64*KST*4)                // 17408
#define AK_B (32*KST*4)                // 8704
#define AV_B (64*VST*4)                // 9216
#define KVSTG2 (AK_B + AV_B)           // 17920
#define P_B (16*PST*4)                 // 2304 per warp
#define POFF (AQ_B + 2*KVSTG2)
#define ATTN_SMEM (POFF + 4*P_B)       // 62464

__global__ __launch_bounds__(128, 3) void attn_mma_kernel()
{
    extern __shared__ char smc[];
    const uint32_t sb = smem_u32(smc);
    const uint32_t kvb = sb + AQ_B;
    const int t = threadIdx.x, lane = t & 31, wid = t >> 5;
    const int rg = lane >> 2, cq = lane & 3;
    const int q0 = blockIdx.x * 64;
    const int h  = blockIdx.y;
    const int b_ = blockIdx.z;
    const size_t headoff = (size_t)(b_*NH + h) * SEQ * DKH;

    const float* Qg  = g_qp  + headoff;
    const float* Kg  = g_kp  + headoff;
    const float* Vtg = g_vpt + headoff;   // [D][SEQ]

    auto kvpre = [&](int kt, int s) {
        const uint32_t stb = kvb + s*KVSTG2;
        #pragma unroll
        for (int u = 0; u < 4; u++) {       // K: 32 rows x 256B
            int idx = t + 128*u, row = idx >> 4, ch = idx & 15;
            cpa16(stb + (row*KST + ch*4)*4, Kg + (size_t)(kt*32 + row)*DKH + ch*4);
        }
        #pragma unroll
        for (int u = 0; u < 4; u++) {       // V^T: 64 rows x 128B
            int idx = t + 128*u, row = idx >> 3, ch = idx & 7;
            cpa16(stb + AK_B + (row*VST + ch*4)*4, Vtg + (size_t)row*SEQ + kt*32 + ch*4);
        }
    };

    kvpre(0, 0); CP_COMMIT();

    // stage Q tile 64x64 fp32
    #pragma unroll
    for (int u = 0; u < 8; u++) {
        int idx = t + 128*u, row = idx >> 4, ch = idx & 15;
        *(uint4*)(smc + (row*KST + ch*4)*4) = *(const uint4*)(Qg + (size_t)(q0 + row)*DKH + ch*4);
    }
    __syncthreads();

    // hoist Q fragments (warp owns rows [16w,16w+16)); tf32 A-frag layout
    uint32_t qf[8][4];
    {
        uint32_t qb = sb + ((16*wid + rg)*KST + cq)*4;
        #pragma unroll
        for (int ks = 0; ks < 8; ks++) {
            qf[ks][0] = lds32(qb + ks*32);
            qf[ks][1] = lds32(qb + ks*32 + 8*KST*4);
            qf[ks][2] = lds32(qb + ks*32 + 16);
            qf[ks][3] = lds32(qb + ks*32 + 8*KST*4 + 16);
        }
    }

    float o[8][4] = {};
    float lsum1 = 0.0f, lsum2 = 0.0f;

    const bf16* mb1 = g_mbias + (size_t)(q0 + 16*wid + rg)*SEQ + 2*cq;
    const bf16* mb2 = mb1 + (size_t)8*SEQ;
    const uint32_t pw = sb + POFF + wid*P_B;

    for (int kt = 0; kt < SEQ/32; kt++) {
        CP_WAIT0();
        __syncthreads();
        if (kt < SEQ/32 - 1) { kvpre(kt + 1, (kt + 1) & 1); CP_COMMIT(); }

        const uint32_t stb = kvb + (kt & 1)*KVSTG2;

        // S = Q K^T : 16q x 32k, tf32
        float s4[4][4] = {};
        #pragma unroll
        for (int ks = 0; ks < 8; ks++) {
            #pragma unroll
            for (int nf = 0; nf < 4; nf++) {
                uint32_t ka = stb + ((nf*8 + rg)*KST + ks*8 + cq)*4;
                uint32_t b0 = lds32(ka);
                uint32_t b1 = lds32(ka + 16);
                mma_tf32(s4[nf], qf[ks], b0, b1);
            }
        }

        // mask + exp (unnormalized)
        #pragma unroll
        for (int nf = 0; nf < 4; nf++) {
            __nv_bfloat162 u1 = *(const __nv_bfloat162*)(mb1 + kt*32 + nf*8);
            __nv_bfloat162 u2 = *(const __nv_bfloat162*)(mb2 + kt*32 + nf*8);
            s4[nf][0] = exp2f(fmaf(s4[nf][0], SCALE_LOG2E, __low2float(u1)));
            s4[nf][1] = exp2f(fmaf(s4[nf][1], SCALE_LOG2E, __high2float(u1)));
            s4[nf][2] = exp2f(fmaf(s4[nf][2], SCALE_LOG2E, __low2float(u2)));
            s4[nf][3] = exp2f(fmaf(s4[nf][3], SCALE_LOG2E, __high2float(u2)));
            lsum1 += s4[nf][0] + s4[nf][1];
            lsum2 += s4[nf][2] + s4[nf][3];
        }

        // store P (tf32-rounded) to per-warp smem buffer
        #pragma unroll
        for (int nf = 0; nf < 4; nf++) {
            sts64(pw + (rg*PST + nf*8 + 2*cq)*4,      tf32u(s4[nf][0]), tf32u(s4[nf][1]));
            sts64(pw + ((rg+8)*PST + nf*8 + 2*cq)*4,  tf32u(s4[nf][2]), tf32u(s4[nf][3]));
        }
        __syncwarp();

        // O += P @ V : tf32 ; A-frags from P buffer, B-frags from V^T
        #pragma unroll
        for (int slab = 0; slab < 4; slab++) {
            uint32_t pa = pw + (rg*PST + slab*8 + cq)*4;
            uint32_t af[4];
            af[0] = lds32(pa);
            af[1] = lds32(pa + 8*PST*4);
            af[2] = lds32(pa + 16);
            af[3] = lds32(pa + 8*PST*4 + 16);
            #pragma unroll
            for (int nf2 = 0; nf2 < 8; nf2++) {
                uint32_t va = stb + AK_B + ((nf2*8 + rg)*VST + slab*8 + cq)*4;
                uint32_t b0 = lds32(va);
                uint32_t b1 = lds32(va + 16);
                mma_tf32(o[nf2], af, b0, b1);
            }
        }
        __syncwarp();
    }

    // reduce row sums across quad lanes
    lsum1 += __shfl_xor_sync(0xffffffffu, lsum1, 1);
    lsum1 += __shfl_xor_sync(0xffffffffu, lsum1, 2);
    lsum2 += __shfl_xor_sync(0xffffffffu, lsum2, 1);
    lsum2 += __shfl_xor_sync(0xffffffffu, lsum2, 2);

    // epilogue: normalize, split hi/lo (bf16) for out-proj
    const float inv1 = 1.0f / lsum1, inv2 = 1.0f / lsum2;
    const int gr = q0 + 16*wid + rg;
    size_t base1 = ((size_t)b_*SEQ + gr)*DMODEL + h*DKH;
    size_t base2 = base1 + (size_t)8*DMODEL;
    #pragma unroll
    for (int nf2 = 0; nf2 < 8; nf2++) {
        const int d0 = nf2*8 + 2*cq;
        float v0 = o[nf2][0]*inv1, v1 = o[nf2][1]*inv1;
        float v2 = o[nf2][2]*inv2, v3 = o[nf2][3]*inv2;
        float h0,l0,h1,l1v;
        hilo(v0,h0,l0); hilo(v1,h1,l1v);
        *(uint32_t*)(g_chi + base1 + d0) = packbf(v0, v1);
        *(uint32_t*)(g_clo + base1 + d0) = packbf(l0, l1v);
        hilo(v2,h0,l0); hilo(v3,h1,l1v);
        *(uint32_t*)(g_chi + base2 + d0) = packbf(v2, v3);
        *(uint32_t*)(g_clo + base2 + d0) = packbf(l0, l1v);
    }
}

// ---------------- launcher ----------------
extern "C" void kernel_launch(void* const* d_in, const int* in_sizes, int n_in,
                              void* d_out, int out_size)
{
    const float* q   = (const float*)d_in[0];
    const float* k   = (const float*)d_in[1];
    const float* v   = (const float*)d_in[2];
    const int*   msk = (const int*)  d_in[3];
    const float* w_q = (const float*)d_in[4];
    const float* b_q = (const float*)d_in[5];
    const float* w_k = (const float*)d_in[6];
    const float* b_k = (const float*)d_in[7];
    const float* w_v = (const float*)d_in[8];
    const float* b_v = (const float*)d_in[9];
    const float* w_o = (const float*)d_in[10];
    const float* b_o = (const float*)d_in[11];
    float* out = (float*)d_out;

    cudaFuncSetAttribute(gemm_mma_kernel<false>, cudaFuncAttributeMaxDynamicSharedMemorySize, GEMM_SMEM);
    cudaFuncSetAttribute(gemm_mma_kernel<true>,  cudaFuncAttributeMaxDynamicSharedMemorySize, GEMM_SMEM);
    cudaFuncSetAttribute(attn_mma_kernel, cudaFuncAttributeMaxDynamicSharedMemorySize, ATTN_SMEM);

    cvt_in_kernel<<<dim3(MROWS*DMODEL/1024, 1, 3), 256>>>(q, k, v);
    cvt_w_kernel<<<dim3(DMODEL*DMODEL/1024, 1, 4), 256>>>(w_q, w_k, w_v, w_o);
    cvt_mask_kernel<<<dim3((size_t)SEQ*SEQ/1024, 1, 1), 256>>>(msk);
    gemm_mma_kernel<false><<<dim3(DMODEL/128, MROWS/256, 3), 256, GEMM_SMEM>>>(b_q, b_k, b_v, b_o, out);
    attn_mma_kernel<<<dim3(SEQ/64, NH, BATCH), 128, ATTN_SMEM>>>();
    gemm_mma_kernel<true><<<dim3(DMODEL/128, MROWS/256, 1), 256, GEMM_SMEM>>>(b_q, b_k, b_v, b_o, out);
}